// round 7
// baseline (speedup 1.0000x reference)
#include <cuda_runtime.h>
#include <cuda_fp16.h>
#include <cstdint>

// Problem shapes (fixed)
#define BSZ 16
#define TT  1024
#define EMB 768
#define HID 1024
#define MROWS (BSZ*TT)   // 16384 rows per tensor

// ======================= scratch (device globals) ==========================
__device__ __align__(128) __half g_ABh [(size_t)2 * MROWS * 2 * EMB];  // split inputs (32768 x 1536)
__device__ __align__(128) __half g_W1Th[(size_t)HID * 2 * EMB];        // W1^T split (1024 x 1536)
__device__ __align__(128) __half g_W2Th[(size_t)HID * 2 * HID];        // W2^T split (1024 x 2048)
__device__ __align__(128) __half g_Hh  [(size_t)2 * MROWS * 2 * HID];  // hidden split (32768 x 2048)
__device__ __align__(128) __half g_Fh  [(size_t)2 * MROWS * 2 * HID];  // MLP out split (32768 x 2048)
__device__ __align__(128) float  g_E   [(size_t)BSZ * TT * TT];        // e (fp32)
__device__ __align__(128) __half g_Ph  [(size_t)BSZ * TT * TT];        // row softmax (half)
__device__ __align__(128) __half g_P2h [(size_t)BSZ * TT * TT];        // col softmax, transposed (tb, ta)
__device__ __align__(128) __half g_ATh [(size_t)BSZ * EMB * TT];       // Ain^T per batch (768 x 1024)
__device__ __align__(128) __half g_BTh [(size_t)BSZ * EMB * TT];       // Bin^T per batch
__device__ float g_rmax[MROWS], g_rsum[MROWS];
__device__ float g_cmax[MROWS], g_csum[MROWS];

// ======================= helpers ===========================================
__device__ __forceinline__ uint32_t smem_u32(const void* p) {
    uint32_t a;
    asm("{ .reg .u64 t; cvta.to.shared.u64 t, %1; cvt.u32.u64 %0, t; }" : "=r"(a) : "l"(p));
    return a;
}
__device__ __forceinline__ void mma_f16(float* d, const uint32_t* a, const uint32_t* b) {
    asm volatile(
        "mma.sync.aligned.m16n8k16.row.col.f32.f16.f16.f32 "
        "{%0,%1,%2,%3}, {%4,%5,%6,%7}, {%8,%9}, {%0,%1,%2,%3};"
        : "+f"(d[0]), "+f"(d[1]), "+f"(d[2]), "+f"(d[3])
        : "r"(a[0]), "r"(a[1]), "r"(a[2]), "r"(a[3]), "r"(b[0]), "r"(b[1]));
}
// fp16-accumulate variant: 2x rate on the legacy tensor pipe
__device__ __forceinline__ void mma_f16acc(uint32_t* d, const uint32_t* a, const uint32_t* b) {
    asm volatile(
        "mma.sync.aligned.m16n8k16.row.col.f16.f16.f16.f16 "
        "{%0,%1}, {%2,%3,%4,%5}, {%6,%7}, {%0,%1};"
        : "+r"(d[0]), "+r"(d[1])
        : "r"(a[0]), "r"(a[1]), "r"(a[2]), "r"(a[3]), "r"(b[0]), "r"(b[1]));
}
__device__ __forceinline__ void ldsm_x4(uint32_t& r0, uint32_t& r1,
                                        uint32_t& r2, uint32_t& r3, uint32_t addr) {
    asm volatile("ldmatrix.sync.aligned.m8n8.x4.shared.b16 {%0,%1,%2,%3}, [%4];"
        : "=r"(r0), "=r"(r1), "=r"(r2), "=r"(r3) : "r"(addr));
}
__device__ __forceinline__ void split_h(float v, __half& hi, __half& lo) {
    hi = __float2half_rn(v);
    lo = __float2half_rn((v - __half2float(hi)) * 2048.0f);
}

// ======================= fp16 mma.sync GEMM ================================
// C(M,N) = [act]( sum_phases A_ph(M,K) * B_ph(N,K)^T [scaled] + bias )
// A, B K-major half. BM=256, BN=128, BK=64 halves. 16 warps = 4(m) x 4(n).
// 3-phase split: ph0 = A_lo*B_hi, ph1 = A_hi*B_lo (lo pre-scaled by 2048),
// both accumulated in FP16 (2x tensor rate), converted to f32 * 2^-11,
// then ph2 = A_hi*B_hi accumulated in FP32.
#define BM 256
#define BN 128
#define BKH 64
#define NTHR 512
#define SSTR 72                            // halves per smem row (LDSM conflict-free)
#define STG_BYTES ((BM + BN) * SSTR * 2)   // 55296
#define STG_A_BYTES (BM * SSTR * 2)        // 36864
#define GEMM_SMEM (3 * STG_BYTES)          // 165888

__device__ __forceinline__ void cp_stage_h(uint32_t stA, uint32_t stB,
    const __half* __restrict__ ga, int lda,
    const __half* __restrict__ gb, int ldb, int tid)
{
#pragma unroll
    for (int i = 0; i < 4; ++i) {                 // A: 256 rows x 8 x 16B
        int u = tid + i * NTHR;
        int r = u >> 3, c = u & 7;
        asm volatile("cp.async.cg.shared.global [%0], [%1], 16;"
            :: "r"(stA + (uint32_t)(r * (SSTR * 2) + c * 16)),
               "l"(ga + (size_t)r * lda + c * 8) : "memory");
    }
#pragma unroll
    for (int i = 0; i < 2; ++i) {                 // B: 128 rows x 8 x 16B
        int u = tid + i * NTHR;
        int r = u >> 3, c = u & 7;
        asm volatile("cp.async.cg.shared.global [%0], [%1], 16;"
            :: "r"(stB + (uint32_t)(r * (SSTR * 2) + c * 16)),
               "l"(gb + (size_t)r * ldb + c * 8) : "memory");
    }
}

template<int NPHASE, bool BIASRELU, bool HALFSPLITOUT>
__global__ void __launch_bounds__(NTHR, 1)
gemm_h(const __half* __restrict__ Aop, int lda, unsigned long long sA,
       const __half* __restrict__ Bop, int ldb, unsigned long long sB,
       const float* __restrict__ bias,
       void* __restrict__ Cv, int ldc, unsigned long long sC,
       int N, int K)
{
    extern __shared__ __align__(128) __half smh[];
    uint32_t sbase = smem_u32(smh);
    const int tid  = threadIdx.x;
    const int lane = tid & 31;
    const int wid  = tid >> 5;
    const int wm   = wid >> 2;        // 0..3 (64 rows each)
    const int wn   = wid & 3;         // 0..3 (32 cols each)
    const int gr   = lane >> 2;       // 0..7 (mma fragment row group)
    const int tc   = lane & 3;        // 0..3
    const int m0 = blockIdx.y * BM;
    const int n0 = blockIdx.x * BN;

    const __half* Abase = Aop + (size_t)blockIdx.z * sA + (size_t)m0 * lda;
    const __half* Bbase = Bop + (size_t)blockIdx.z * sB + (size_t)n0 * ldb;

    const int KB = K / BKH;
    const int NT = NPHASE * KB;
    const int SPLIT_KT = (NPHASE == 3) ? 2 * KB : 0;
    const int aoff0 = (NPHASE == 3) ? K : 0;     // phase0: A_lo
    const int boff1 = (NPHASE == 3) ? K : 0;     // phase1: B_lo

    // ---- per-lane LDSM base offsets (bytes, relative to stage A/B bases) --
    const int lg = lane >> 3;          // ldmatrix lane group 0..3
    const int r8 = lane & 7;
    uint32_t aOff[4], bOff[2];
#pragma unroll
    for (int mi = 0; mi < 4; ++mi)     // A: m8 blocks via (lg&1), k+8 via (lg>>1)
        aOff[mi] = (uint32_t)(((wm * 64 + mi * 16 + (lg & 1) * 8 + r8) * SSTR
                               + (lg >> 1) * 8) * 2);
#pragma unroll
    for (int pn = 0; pn < 2; ++pn)     // B: k+8 via (lg&1), n+8 via (lg>>1)
        bOff[pn] = (uint32_t)(((wn * 32 + pn * 16 + (lg >> 1) * 8 + r8) * SSTR
                               + (lg & 1) * 8) * 2);

    // prefetch helper
    auto prefetch = [&](int nt) {
        if (nt < NT) {
            int ph = nt / KB;
            int kk = nt - ph * KB;
            int oa = (ph == 0) ? aoff0 : 0;
            int ob = (ph == 1) ? boff1 : 0;
            uint32_t st = sbase + (uint32_t)(nt % 3) * STG_BYTES;
            cp_stage_h(st, st + STG_A_BYTES,
                       Abase + oa + kk * BKH, lda, Bbase + ob + kk * BKH, ldb, tid);
        }
        asm volatile("cp.async.commit_group;" ::: "memory");
    };
    auto ldfrags = [&](int kt, int ks, uint32_t af[4][4], uint32_t bf[4][2]) {
        uint32_t stA = sbase + (uint32_t)(kt % 3) * STG_BYTES;
        uint32_t stB = stA + STG_A_BYTES;
        const uint32_t kb = (uint32_t)(ks * 32);   // 16 halves per ks
#pragma unroll
        for (int pn = 0; pn < 2; ++pn) {
            uint32_t t0, t1, t2, t3;
            ldsm_x4(t0, t1, t2, t3, stB + bOff[pn] + kb);
            bf[2 * pn][0] = t0;  bf[2 * pn][1] = t1;
            bf[2 * pn + 1][0] = t2;  bf[2 * pn + 1][1] = t3;
        }
#pragma unroll
        for (int mi = 0; mi < 4; ++mi)
            ldsm_x4(af[mi][0], af[mi][1], af[mi][2], af[mi][3],
                    stA + aOff[mi] + kb);
    };

    float acc[4][4][4];

    // prologue: stages 0, 1
#pragma unroll 1
    for (int s = 0; s < 2; ++s) {
        uint32_t st = sbase + (uint32_t)s * STG_BYTES;
        cp_stage_h(st, st + STG_A_BYTES,
                   Abase + aoff0 + s * BKH, lda, Bbase + s * BKH, ldb, tid);
        asm volatile("cp.async.commit_group;" ::: "memory");
    }

    if (NPHASE == 3) {
        // ---- phases 0,1: fp16 accumulate (2x tensor rate) ------------------
        uint32_t acc16[4][4][2];
#pragma unroll
        for (int i = 0; i < 4; ++i)
#pragma unroll
            for (int j = 0; j < 4; ++j) { acc16[i][j][0] = 0u; acc16[i][j][1] = 0u; }

#pragma unroll 1
        for (int kt = 0; kt < SPLIT_KT; ++kt) {
            asm volatile("cp.async.wait_group 1;" ::: "memory");
            __syncthreads();
            prefetch(kt + 2);
#pragma unroll
            for (int ks = 0; ks < 4; ++ks) {
                uint32_t af[4][4], bf[4][2];
                ldfrags(kt, ks, af, bf);
#pragma unroll
                for (int mi = 0; mi < 4; ++mi)
#pragma unroll
                    for (int ni = 0; ni < 4; ++ni)
                        mma_f16acc(acc16[mi][ni], af[mi], bf[ni]);
            }
        }
        // convert f16 acc -> f32 acc, scaled by 2^-11
#pragma unroll
        for (int mi = 0; mi < 4; ++mi)
#pragma unroll
            for (int ni = 0; ni < 4; ++ni) {
                __half2 h0 = *reinterpret_cast<__half2*>(&acc16[mi][ni][0]);
                __half2 h1 = *reinterpret_cast<__half2*>(&acc16[mi][ni][1]);
                float2 f0 = __half22float2(h0);
                float2 f1 = __half22float2(h1);
                acc[mi][ni][0] = f0.x * 4.8828125e-4f;
                acc[mi][ni][1] = f0.y * 4.8828125e-4f;
                acc[mi][ni][2] = f1.x * 4.8828125e-4f;
                acc[mi][ni][3] = f1.y * 4.8828125e-4f;
            }
    } else {
#pragma unroll
        for (int i = 0; i < 4; ++i)
#pragma unroll
            for (int j = 0; j < 4; ++j)
#pragma unroll
                for (int k = 0; k < 4; ++k) acc[i][j][k] = 0.f;
    }

    // ---- final phase: fp32 accumulate --------------------------------------
#pragma unroll 1
    for (int kt = SPLIT_KT; kt < NT; ++kt) {
        asm volatile("cp.async.wait_group 1;" ::: "memory");
        __syncthreads();
        prefetch(kt + 2);
#pragma unroll
        for (int ks = 0; ks < 4; ++ks) {
            uint32_t af[4][4], bf[4][2];
            ldfrags(kt, ks, af, bf);
#pragma unroll
            for (int mi = 0; mi < 4; ++mi)
#pragma unroll
                for (int ni = 0; ni < 4; ++ni)
                    mma_f16(acc[mi][ni], af[mi], bf[ni]);
        }
    }

    // ---- epilogue --------------------------------------------------------
#pragma unroll
    for (int ni = 0; ni < 4; ++ni) {
        int col = n0 + wn * 32 + ni * 8 + 2 * tc;
        float b0 = 0.f, b1 = 0.f;
        if (BIASRELU) { b0 = __ldg(bias + col); b1 = __ldg(bias + col + 1); }
#pragma unroll
        for (int mi = 0; mi < 4; ++mi) {
            int row0 = m0 + wm * 64 + mi * 16 + gr;
            float v00 = acc[mi][ni][0], v01 = acc[mi][ni][1];
            float v10 = acc[mi][ni][2], v11 = acc[mi][ni][3];
            if (BIASRELU) {
                v00 = fmaxf(v00 + b0, 0.f); v01 = fmaxf(v01 + b1, 0.f);
                v10 = fmaxf(v10 + b0, 0.f); v11 = fmaxf(v11 + b1, 0.f);
            }
            if (HALFSPLITOUT) {
                __half* C = (__half*)Cv + (size_t)blockIdx.z * sC;
                __half h00, l00, h01, l01, h10, l10, h11, l11;
                split_h(v00, h00, l00); split_h(v01, h01, l01);
                split_h(v10, h10, l10); split_h(v11, h11, l11);
                __half* p0 = C + (size_t)row0 * ldc + col;
                __half* p1 = C + (size_t)(row0 + 8) * ldc + col;
                *(__half2*)p0       = __halves2half2(h00, h01);
                *(__half2*)(p0 + N) = __halves2half2(l00, l01);
                *(__half2*)p1       = __halves2half2(h10, h11);
                *(__half2*)(p1 + N) = __halves2half2(l10, l11);
            } else {
                float* C = (float*)Cv + (size_t)blockIdx.z * sC;
                *(float2*)(C + (size_t)row0 * ldc + col)       = make_float2(v00, v01);
                *(float2*)(C + (size_t)(row0 + 8) * ldc + col) = make_float2(v10, v11);
            }
        }
    }
}

// ======================= fused prep kernel =================================
#define NSPA ((MROWS * EMB) / 1024)            // 12288 (256 thr x float4)
#define NW1  ((EMB / 32) * (HID / 32))         // 768
#define NW2  ((HID / 32) * (HID / 32))         // 1024
#define NAT  (BSZ * (TT / 32) * (EMB / 32))    // 12288
#define PREP_BLOCKS (2 * NSPA + NW1 + NW2 + 2 * NAT)

__global__ void __launch_bounds__(256)
prep_kernel(const float* __restrict__ A, const float* __restrict__ Bn,
            const float* __restrict__ W1, const float* __restrict__ W2,
            __half* __restrict__ ABh, __half* __restrict__ W1Th,
            __half* __restrict__ W2Th, __half* __restrict__ ATh,
            __half* __restrict__ BTh)
{
    __shared__ float tile[32][33];
    int id = blockIdx.x;
    int tid = threadIdx.x;

    if (id < 2 * NSPA) {                       // -------- input splits
        bool isA = id < NSPA;
        const float4* src = (const float4*)(isA ? A : Bn);
        size_t rowoff = isA ? 0 : (size_t)MROWS;
        size_t i = (size_t)(id - (isA ? 0 : NSPA)) * 256 + tid;
        float4 v = src[i];
        size_t row = i / (EMB / 4), c = (i % (EMB / 4)) * 4;
        __half h0, l0, h1, l1, h2, l2, h3, l3;
        split_h(v.x, h0, l0); split_h(v.y, h1, l1);
        split_h(v.z, h2, l2); split_h(v.w, h3, l3);
        __half* dst = ABh + (row + rowoff) * (2 * EMB) + c;
        *(__half2*)dst           = __halves2half2(h0, h1);
        *(__half2*)(dst + 2)     = __halves2half2(h2, h3);
        *(__half2*)(dst + EMB)   = __halves2half2(l0, l1);
        *(__half2*)(dst + EMB+2) = __halves2half2(l2, l3);
        return;
    }
    id -= 2 * NSPA;

    int tx = tid & 31, ty = tid >> 5;
    if (id < NW1 + NW2) {                      // -------- weight transpose+split
        bool isW1 = id < NW1;
        int id2 = isW1 ? id : id - NW1;
        int R = isW1 ? EMB : HID;
        const float* W = isW1 ? W1 : W2;
        __half* WT = isW1 ? W1Th : W2Th;
        int rt = R / 32;
        int r0 = (id2 % rt) * 32, c0 = (id2 / rt) * 32;
#pragma unroll
        for (int k = 0; k < 4; ++k)
            tile[k * 8 + ty][tx] = W[(size_t)(r0 + k * 8 + ty) * HID + c0 + tx];
        __syncthreads();
#pragma unroll
        for (int k = 0; k < 4; ++k) {
            int c = c0 + k * 8 + ty;
            float v = tile[tx][k * 8 + ty];
            __half h, l; split_h(v, h, l);
            WT[(size_t)c * (2 * R) + r0 + tx]     = h;
            WT[(size_t)c * (2 * R) + R + r0 + tx] = l;
        }
        return;
    }
    id -= NW1 + NW2;

    {                                          // -------- AT / BT transposes
        bool isA = id < NAT;
        int id2 = isA ? id : id - NAT;
        const float* X = (isA ? A : Bn);
        __half* XT = (isA ? ATh : BTh);
        int batch = id2 / (NAT / BSZ);
        int t = id2 % (NAT / BSZ);
        int r0 = (t % 32) * 32, c0 = (t / 32) * 32;
        X  += (size_t)batch * TT * EMB;
        XT += (size_t)batch * EMB * TT;
#pragma unroll
        for (int k = 0; k < 4; ++k)
            tile[k * 8 + ty][tx] = X[(size_t)(r0 + k * 8 + ty) * EMB + c0 + tx];
        __syncthreads();
#pragma unroll
        for (int k = 0; k < 4; ++k) {
            int c = c0 + k * 8 + ty;
            XT[(size_t)c * TT + r0 + tx] = __float2half_rn(tile[tx][k * 8 + ty]);
        }
    }
}

// ---------------- softmax stats + normalize --------------------------------
__global__ void __launch_bounds__(256)
rowstats_kernel(const float* __restrict__ E, float* __restrict__ rmax, float* __restrict__ rsum)
{
    int r = blockIdx.x * 8 + (threadIdx.x >> 5);
    int lane = threadIdx.x & 31;
    const float* row = E + (size_t)r * TT;
    float v[32];
    float m = -1e30f;
#pragma unroll
    for (int i = 0; i < 8; ++i) {
        float4 t = *reinterpret_cast<const float4*>(row + i * 128 + lane * 4);
        v[i*4+0]=t.x; v[i*4+1]=t.y; v[i*4+2]=t.z; v[i*4+3]=t.w;
        m = fmaxf(m, fmaxf(fmaxf(t.x, t.y), fmaxf(t.z, t.w)));
    }
#pragma unroll
    for (int o = 16; o > 0; o >>= 1) m = fmaxf(m, __shfl_xor_sync(0xffffffffu, m, o));
    float s = 0.f;
#pragma unroll
    for (int i = 0; i < 32; ++i) s += __expf(v[i] - m);
#pragma unroll
    for (int o = 16; o > 0; o >>= 1) s += __shfl_xor_sync(0xffffffffu, s, o);
    if (lane == 0) { rmax[r] = m; rsum[r] = s; }
}

__global__ void __launch_bounds__(256)
colstats_kernel(const float* __restrict__ E, float* __restrict__ cmax, float* __restrict__ csum)
{
    int b = blockIdx.x >> 2;
    int c = ((blockIdx.x & 3) << 8) + threadIdx.x;
    const float* base = E + (size_t)b * TT * TT + c;
    float m = -1e30f;
#pragma unroll 8
    for (int a = 0; a < TT; ++a) m = fmaxf(m, base[(size_t)a * TT]);
    float s = 0.f;
#pragma unroll 8
    for (int a = 0; a < TT; ++a) s += __expf(base[(size_t)a * TT] - m);
    cmax[b * TT + c] = m;
    csum[b * TT + c] = s;
}

__global__ void __launch_bounds__(256)
normexp_kernel(const float* __restrict__ E, __half* __restrict__ P, __half* __restrict__ P2,
               const float* __restrict__ rmax, const float* __restrict__ rsum,
               const float* __restrict__ cmax, const float* __restrict__ csum)
{
    __shared__ float tile[32][33];
    int b = blockIdx.z;
    int a0 = blockIdx.y * 32, c0 = blockIdx.x * 32;
    int tx = threadIdx.x, ty = threadIdx.y;
    const float* Eb = E + (size_t)b * TT * TT;
    __half* Pb  = P  + (size_t)b * TT * TT;
    __half* P2b = P2 + (size_t)b * TT * TT;
#pragma unroll
    for (int k = 0; k < 4; ++k) {
        int a = a0 + k * 8 + ty;
        float v = Eb[(size_t)a * TT + c0 + tx];
        tile[k * 8 + ty][tx] = v;
        int gr = b * TT + a;
        Pb[(size_t)a * TT + c0 + tx] =
            __float2half_rn(__expf(v - rmax[gr]) * __frcp_rn(rsum[gr]));
    }
    __syncthreads();
#pragma unroll
    for (int k = 0; k < 4; ++k) {
        int c = c0 + k * 8 + ty;
        float v = tile[tx][k * 8 + ty];
        int gc = b * TT + c;
        P2b[(size_t)c * TT + a0 + tx] =
            __float2half_rn(__expf(v - cmax[gc]) * __frcp_rn(csum[gc]));
    }
}

// ======================= launch ============================================
extern "C" void kernel_launch(void* const* d_in, const int* in_sizes, int n_in,
                              void* d_out, int out_size)
{
    const float* Ain = (const float*)d_in[0];
    const float* Bin = (const float*)d_in[1];
    const float* W1  = (const float*)d_in[2];
    const float* b1  = (const float*)d_in[3];
    const float* W2  = (const float*)d_in[4];
    const float* b2  = (const float*)d_in[5];
    float* outp = (float*)d_out;

    __half *ABh, *W1Th, *W2Th, *Hh, *Fh, *Ph, *P2h, *ATh, *BTh;
    float *E, *rm, *rs, *cm, *cs;
    cudaGetSymbolAddress((void**)&ABh,  g_ABh);
    cudaGetSymbolAddress((void**)&W1Th, g_W1Th);
    cudaGetSymbolAddress((void**)&W2Th, g_W2Th);
    cudaGetSymbolAddress((void**)&Hh,   g_Hh);
    cudaGetSymbolAddress((void**)&Fh,   g_Fh);
    cudaGetSymbolAddress((void**)&E,    g_E);
    cudaGetSymbolAddress((void**)&Ph,   g_Ph);
    cudaGetSymbolAddress((void**)&P2h,  g_P2h);
    cudaGetSymbolAddress((void**)&ATh,  g_ATh);
    cudaGetSymbolAddress((void**)&BTh,  g_BTh);
    cudaGetSymbolAddress((void**)&rm,   g_rmax);
    cudaGetSymbolAddress((void**)&rs,   g_rsum);
    cudaGetSymbolAddress((void**)&cm,   g_cmax);
    cudaGetSymbolAddress((void**)&cs,   g_csum);

    cudaFuncSetAttribute(gemm_h<3, true,  true >, cudaFuncAttributeMaxDynamicSharedMemorySize, GEMM_SMEM);
    cudaFuncSetAttribute(gemm_h<3, false, false>, cudaFuncAttributeMaxDynamicSharedMemorySize, GEMM_SMEM);
    cudaFuncSetAttribute(gemm_h<1, false, false>, cudaFuncAttributeMaxDynamicSharedMemorySize, GEMM_SMEM);

    // 1) operand prep (single fused kernel)
    prep_kernel<<<PREP_BLOCKS, 256>>>(Ain, Bin, W1, W2, ABh, W1Th, W2Th, ATh, BTh);

    // 2) MLP layer 1 (A and B rows together): Hh = split(relu(X @ W1 + b1))
    gemm_h<3, true, true><<<dim3(HID/BN, 2*MROWS/BM, 1), NTHR, GEMM_SMEM>>>(
        ABh, 2*EMB, 0, W1Th, 2*EMB, 0, b1, Hh, 2*HID, 0, HID, EMB);

    // 3) MLP layer 2: Fh = split(relu(Hh @ W2 + b2))
    gemm_h<3, true, true><<<dim3(HID/BN, 2*MROWS/BM, 1), NTHR, GEMM_SMEM>>>(
        Hh, 2*HID, 0, W2Th, 2*HID, 0, b2, Fh, 2*HID, 0, HID, HID);

    // 4) e[b] = f_A[b] @ f_B[b]^T (fp32 out)
    gemm_h<3, false, false><<<dim3(TT/BN, TT/BM, BSZ), NTHR, GEMM_SMEM>>>(
        Fh, 2*HID, (unsigned long long)TT * 2 * HID,
        Fh + (size_t)MROWS * 2 * HID, 2*HID, (unsigned long long)TT * 2 * HID,
        nullptr, E, TT, (unsigned long long)TT * TT, TT, HID);

    // 5-7) softmaxes
    rowstats_kernel<<<MROWS/8, 256>>>(E, rm, rs);
    colstats_kernel<<<BSZ*4, 256>>>(E, cm, cs);
    normexp_kernel<<<dim3(TT/32, TT/32, BSZ), dim3(32, 8)>>>(E, Ph, P2h, rm, rs, cm, cs);

    // 8) beta = P @ B
    gemm_h<1, false, false><<<dim3(EMB/BN, TT/BM, BSZ), NTHR, GEMM_SMEM>>>(
        Ph, TT, (unsigned long long)TT * TT, BTh, TT, (unsigned long long)EMB * TT,
        nullptr, outp, EMB, (unsigned long long)TT * EMB, EMB, TT);

    // 9) alpha = P2 @ A
    gemm_h<1, false, false><<<dim3(EMB/BN, TT/BM, BSZ), NTHR, GEMM_SMEM>>>(
        P2h, TT, (unsigned long long)TT * TT, ATh, TT, (unsigned long long)EMB * TT,
        nullptr, outp + (size_t)BSZ * TT * EMB, EMB, (unsigned long long)TT * EMB, EMB, TT);
}

// round 8
// speedup vs baseline: 1.1462x; 1.1462x over previous
#include <cuda_runtime.h>
#include <cuda_fp16.h>
#include <cstdint>

// Problem shapes (fixed)
#define BSZ 16
#define TT  1024
#define EMB 768
#define HID 1024
#define MROWS (BSZ*TT)   // 16384 rows per tensor

// ======================= scratch (device globals) ==========================
__device__ __align__(128) __half g_ABh [(size_t)2 * MROWS * 2 * EMB];  // split inputs (32768 x 1536)
__device__ __align__(128) __half g_W1Th[(size_t)HID * 2 * EMB];        // W1^T split (1024 x 1536)
__device__ __align__(128) __half g_W2Th[(size_t)HID * 2 * HID];        // W2^T split (1024 x 2048)
__device__ __align__(128) __half g_Hh  [(size_t)2 * MROWS * 2 * HID];  // hidden split (32768 x 2048)
__device__ __align__(128) __half g_Fh  [(size_t)2 * MROWS * 2 * HID];  // MLP out split (32768 x 2048)
__device__ __align__(128) float  g_E   [(size_t)BSZ * TT * TT];        // e (fp32)
// P (row softmax) then P2 (col softmax, transposed) contiguous: 32 batches
__device__ __align__(128) __half g_Pall[(size_t)2 * BSZ * TT * TT];
// BT then AT contiguous: 32 batches of (EMB x TT)
__device__ __align__(128) __half g_Tall[(size_t)2 * BSZ * EMB * TT];
__device__ float g_rmax[MROWS], g_rsum[MROWS];
__device__ float g_cmax[MROWS], g_csum[MROWS];

// ======================= helpers ===========================================
__device__ __forceinline__ uint32_t smem_u32(const void* p) {
    uint32_t a;
    asm("{ .reg .u64 t; cvta.to.shared.u64 t, %1; cvt.u32.u64 %0, t; }" : "=r"(a) : "l"(p));
    return a;
}
__device__ __forceinline__ void mma_f16(float* d, const uint32_t* a, const uint32_t* b) {
    asm volatile(
        "mma.sync.aligned.m16n8k16.row.col.f32.f16.f16.f32 "
        "{%0,%1,%2,%3}, {%4,%5,%6,%7}, {%8,%9}, {%0,%1,%2,%3};"
        : "+f"(d[0]), "+f"(d[1]), "+f"(d[2]), "+f"(d[3])
        : "r"(a[0]), "r"(a[1]), "r"(a[2]), "r"(a[3]), "r"(b[0]), "r"(b[1]));
}
__device__ __forceinline__ void ldsm_x4(uint32_t& r0, uint32_t& r1,
                                        uint32_t& r2, uint32_t& r3, uint32_t addr) {
    asm volatile("ldmatrix.sync.aligned.m8n8.x4.shared.b16 {%0,%1,%2,%3}, [%4];"
        : "=r"(r0), "=r"(r1), "=r"(r2), "=r"(r3) : "r"(addr));
}
__device__ __forceinline__ void split_h(float v, __half& hi, __half& lo) {
    hi = __float2half_rn(v);
    lo = __float2half_rn((v - __half2float(hi)) * 2048.0f);
}

// ======================= fp16 mma.sync GEMM ================================
// C(M,N) = [act]( sum_phases A_ph(M,K) * B_ph(N,K)^T [scaled] + bias )
// A, B K-major half. BM=128, BN=128, BK=64 halves. 8 warps = 2(m) x 4(n),
// warp tile 64x32. smem 110.6KB -> 2 CTAs/SM (tail smoothing + overlap).
// 3-phase split: ph0 = A_lo*B_hi, ph1 = A_hi*B_lo (lo pre-scaled by 2048),
// then acc *= 2^-11, then ph2 = A_hi*B_hi. All FP32 accumulate.
#define BM 128
#define BN 128
#define BKH 64
#define NTHR 256
#define SSTR 72                            // halves per smem row (LDSM conflict-free)
#define STG_BYTES ((BM + BN) * SSTR * 2)   // 36864
#define STG_A_BYTES (BM * SSTR * 2)        // 18432
#define GEMM_SMEM (3 * STG_BYTES)          // 110592

__device__ __forceinline__ void cp_stage_h(uint32_t stA, uint32_t stB,
    const __half* __restrict__ ga, int lda,
    const __half* __restrict__ gb, int ldb, int tid)
{
#pragma unroll
    for (int i = 0; i < 4; ++i) {                 // A: 128 rows x 8 x 16B
        int u = tid + i * NTHR;
        int r = u >> 3, c = u & 7;
        asm volatile("cp.async.cg.shared.global [%0], [%1], 16;"
            :: "r"(stA + (uint32_t)(r * (SSTR * 2) + c * 16)),
               "l"(ga + (size_t)r * lda + c * 8) : "memory");
    }
#pragma unroll
    for (int i = 0; i < 4; ++i) {                 // B: 128 rows x 8 x 16B
        int u = tid + i * NTHR;
        int r = u >> 3, c = u & 7;
        asm volatile("cp.async.cg.shared.global [%0], [%1], 16;"
            :: "r"(stB + (uint32_t)(r * (SSTR * 2) + c * 16)),
               "l"(gb + (size_t)r * ldb + c * 8) : "memory");
    }
}

template<int NPHASE, bool BIASRELU, bool HALFSPLITOUT>
__global__ void __launch_bounds__(NTHR, 2)
gemm_h(const __half* __restrict__ Aop, int lda, unsigned long long sA,
       const __half* __restrict__ Bop, int ldb, unsigned long long sB,
       const float* __restrict__ bias,
       void* __restrict__ Cv, int ldc, unsigned long long sC,
       int N, int K)
{
    extern __shared__ __align__(128) __half smh[];
    uint32_t sbase = smem_u32(smh);
    const int tid  = threadIdx.x;
    const int lane = tid & 31;
    const int wid  = tid >> 5;
    const int wm   = wid >> 2;        // 0..1 (64 rows each)
    const int wn   = wid & 3;         // 0..3 (32 cols each)
    const int gr   = lane >> 2;       // 0..7 (mma fragment row group)
    const int tc   = lane & 3;        // 0..3
    const int m0 = blockIdx.y * BM;
    const int n0 = blockIdx.x * BN;

    const __half* Abase = Aop + (size_t)blockIdx.z * sA + (size_t)m0 * lda;
    const __half* Bbase = Bop + (size_t)blockIdx.z * sB + (size_t)n0 * ldb;

    const int KB = K / BKH;
    const int NT = NPHASE * KB;
    const int aoff0 = (NPHASE == 3) ? K : 0;     // phase0: A_lo
    const int boff1 = (NPHASE == 3) ? K : 0;     // phase1: B_lo

    // ---- per-lane LDSM base offsets (bytes, relative to stage A/B bases) --
    const int lg = lane >> 3;          // ldmatrix lane group 0..3
    const int r8 = lane & 7;
    uint32_t aOff[4], bOff[2];
#pragma unroll
    for (int mi = 0; mi < 4; ++mi)     // A: m8 blocks via (lg&1), k+8 via (lg>>1)
        aOff[mi] = (uint32_t)(((wm * 64 + mi * 16 + (lg & 1) * 8 + r8) * SSTR
                               + (lg >> 1) * 8) * 2);
#pragma unroll
    for (int pn = 0; pn < 2; ++pn)     // B: k+8 via (lg&1), n+8 via (lg>>1)
        bOff[pn] = (uint32_t)(((wn * 32 + pn * 16 + (lg >> 1) * 8 + r8) * SSTR
                               + (lg & 1) * 8) * 2);

    float acc[4][4][4];
#pragma unroll
    for (int i = 0; i < 4; ++i)
#pragma unroll
        for (int j = 0; j < 4; ++j)
#pragma unroll
            for (int k = 0; k < 4; ++k) acc[i][j][k] = 0.f;

    // prologue: stages 0, 1 (both phase 0; KB >= 12 always here)
#pragma unroll 1
    for (int s = 0; s < 2; ++s) {
        uint32_t st = sbase + (uint32_t)s * STG_BYTES;
        cp_stage_h(st, st + STG_A_BYTES,
                   Abase + aoff0 + s * BKH, lda, Bbase + s * BKH, ldb, tid);
        asm volatile("cp.async.commit_group;" ::: "memory");
    }

#pragma unroll 1
    for (int kt = 0; kt < NT; ++kt) {
        asm volatile("cp.async.wait_group 1;" ::: "memory");
        __syncthreads();

        // prefetch kt+2
        {
            int nt = kt + 2;
            if (nt < NT) {
                int ph = nt / KB;
                int kk = nt - ph * KB;
                int oa = (ph == 0) ? aoff0 : 0;
                int ob = (ph == 1) ? boff1 : 0;
                uint32_t st = sbase + (uint32_t)(nt % 3) * STG_BYTES;
                cp_stage_h(st, st + STG_A_BYTES,
                           Abase + oa + kk * BKH, lda, Bbase + ob + kk * BKH, ldb, tid);
            }
            asm volatile("cp.async.commit_group;" ::: "memory");
        }

        // scale accumulated cross terms by 2^-11 at the phase-2 boundary
        if (NPHASE == 3 && kt == 2 * KB) {
#pragma unroll
            for (int i = 0; i < 4; ++i)
#pragma unroll
                for (int j = 0; j < 4; ++j)
#pragma unroll
                    for (int k = 0; k < 4; ++k) acc[i][j][k] *= 4.8828125e-4f;
        }

        uint32_t stA = sbase + (uint32_t)(kt % 3) * STG_BYTES;
        uint32_t stB = stA + STG_A_BYTES;
#pragma unroll
        for (int ks = 0; ks < 4; ++ks) {
            const uint32_t kb = (uint32_t)(ks * 32);   // 16 halves per ks
            uint32_t af[4][4];
            uint32_t bf[4][2];
#pragma unroll
            for (int pn = 0; pn < 2; ++pn) {
                uint32_t t0, t1, t2, t3;
                ldsm_x4(t0, t1, t2, t3, stB + bOff[pn] + kb);
                bf[2 * pn][0] = t0;  bf[2 * pn][1] = t1;
                bf[2 * pn + 1][0] = t2;  bf[2 * pn + 1][1] = t3;
            }
#pragma unroll
            for (int mi = 0; mi < 4; ++mi)
                ldsm_x4(af[mi][0], af[mi][1], af[mi][2], af[mi][3],
                        stA + aOff[mi] + kb);
#pragma unroll
            for (int mi = 0; mi < 4; ++mi)
#pragma unroll
                for (int ni = 0; ni < 4; ++ni)
                    mma_f16(acc[mi][ni], af[mi], bf[ni]);
        }
    }

    // ---- epilogue --------------------------------------------------------
#pragma unroll
    for (int ni = 0; ni < 4; ++ni) {
        int col = n0 + wn * 32 + ni * 8 + 2 * tc;
        float b0 = 0.f, b1 = 0.f;
        if (BIASRELU) { b0 = __ldg(bias + col); b1 = __ldg(bias + col + 1); }
#pragma unroll
        for (int mi = 0; mi < 4; ++mi) {
            int row0 = m0 + wm * 64 + mi * 16 + gr;
            float v00 = acc[mi][ni][0], v01 = acc[mi][ni][1];
            float v10 = acc[mi][ni][2], v11 = acc[mi][ni][3];
            if (BIASRELU) {
                v00 = fmaxf(v00 + b0, 0.f); v01 = fmaxf(v01 + b1, 0.f);
                v10 = fmaxf(v10 + b0, 0.f); v11 = fmaxf(v11 + b1, 0.f);
            }
            if (HALFSPLITOUT) {
                __half* C = (__half*)Cv + (size_t)blockIdx.z * sC;
                __half h00, l00, h01, l01, h10, l10, h11, l11;
                split_h(v00, h00, l00); split_h(v01, h01, l01);
                split_h(v10, h10, l10); split_h(v11, h11, l11);
                __half* p0 = C + (size_t)row0 * ldc + col;
                __half* p1 = C + (size_t)(row0 + 8) * ldc + col;
                *(__half2*)p0       = __halves2half2(h00, h01);
                *(__half2*)(p0 + N) = __halves2half2(l00, l01);
                *(__half2*)p1       = __halves2half2(h10, h11);
                *(__half2*)(p1 + N) = __halves2half2(l10, l11);
            } else {
                float* C = (float*)Cv + (size_t)blockIdx.z * sC;
                *(float2*)(C + (size_t)row0 * ldc + col)       = make_float2(v00, v01);
                *(float2*)(C + (size_t)(row0 + 8) * ldc + col) = make_float2(v10, v11);
            }
        }
    }
}

// ======================= fused prep kernel =================================
#define NSPA ((MROWS * EMB) / 1024)            // 12288 (256 thr x float4)
#define NW1  ((EMB / 32) * (HID / 32))         // 768
#define NW2  ((HID / 32) * (HID / 32))         // 1024
#define NAT  (BSZ * (TT / 32) * (EMB / 32))    // 12288
#define PREP_BLOCKS (2 * NSPA + NW1 + NW2 + 2 * NAT)

__global__ void __launch_bounds__(256)
prep_kernel(const float* __restrict__ A, const float* __restrict__ Bn,
            const float* __restrict__ W1, const float* __restrict__ W2,
            __half* __restrict__ ABh, __half* __restrict__ W1Th,
            __half* __restrict__ W2Th, __half* __restrict__ Tall)
{
    __shared__ float tile[32][33];
    int id = blockIdx.x;
    int tid = threadIdx.x;

    if (id < 2 * NSPA) {                       // -------- input splits
        bool isA = id < NSPA;
        const float4* src = (const float4*)(isA ? A : Bn);
        size_t rowoff = isA ? 0 : (size_t)MROWS;
        size_t i = (size_t)(id - (isA ? 0 : NSPA)) * 256 + tid;
        float4 v = src[i];
        size_t row = i / (EMB / 4), c = (i % (EMB / 4)) * 4;
        __half h0, l0, h1, l1, h2, l2, h3, l3;
        split_h(v.x, h0, l0); split_h(v.y, h1, l1);
        split_h(v.z, h2, l2); split_h(v.w, h3, l3);
        __half* dst = ABh + (row + rowoff) * (2 * EMB) + c;
        *(__half2*)dst           = __halves2half2(h0, h1);
        *(__half2*)(dst + 2)     = __halves2half2(h2, h3);
        *(__half2*)(dst + EMB)   = __halves2half2(l0, l1);
        *(__half2*)(dst + EMB+2) = __halves2half2(l2, l3);
        return;
    }
    id -= 2 * NSPA;

    int tx = tid & 31, ty = tid >> 5;
    if (id < NW1 + NW2) {                      // -------- weight transpose+split
        bool isW1 = id < NW1;
        int id2 = isW1 ? id : id - NW1;
        int R = isW1 ? EMB : HID;
        const float* W = isW1 ? W1 : W2;
        __half* WT = isW1 ? W1Th : W2Th;
        int rt = R / 32;
        int r0 = (id2 % rt) * 32, c0 = (id2 / rt) * 32;
#pragma unroll
        for (int k = 0; k < 4; ++k)
            tile[k * 8 + ty][tx] = W[(size_t)(r0 + k * 8 + ty) * HID + c0 + tx];
        __syncthreads();
#pragma unroll
        for (int k = 0; k < 4; ++k) {
            int c = c0 + k * 8 + ty;
            float v = tile[tx][k * 8 + ty];
            __half h, l; split_h(v, h, l);
            WT[(size_t)c * (2 * R) + r0 + tx]     = h;
            WT[(size_t)c * (2 * R) + R + r0 + tx] = l;
        }
        return;
    }
    id -= NW1 + NW2;

    {   // ---- BT (first 16 batches of Tall) then AT (next 16) transposes ---
        bool isB = id < NAT;                   // beta consumes BT -> z 0..15
        int id2 = isB ? id : id - NAT;
        const float* X = (isB ? Bn : A);
        __half* XT = Tall + (isB ? 0 : (size_t)BSZ * EMB * TT);
        int batch = id2 / (NAT / BSZ);
        int t = id2 % (NAT / BSZ);
        int r0 = (t % 32) * 32, c0 = (t / 32) * 32;
        X  += (size_t)batch * TT * EMB;
        XT += (size_t)batch * EMB * TT;
#pragma unroll
        for (int k = 0; k < 4; ++k)
            tile[k * 8 + ty][tx] = X[(size_t)(r0 + k * 8 + ty) * EMB + c0 + tx];
        __syncthreads();
#pragma unroll
        for (int k = 0; k < 4; ++k) {
            int c = c0 + k * 8 + ty;
            XT[(size_t)c * TT + r0 + tx] = __float2half_rn(tile[tx][k * 8 + ty]);
        }
    }
}

// ---------------- merged softmax stats (row + col in one launch) -----------
#define ROWSTAT_BLOCKS (MROWS / 8)
#define COLSTAT_BLOCKS (BSZ * 4)

__global__ void __launch_bounds__(256)
stats_kernel(const float* __restrict__ E,
             float* __restrict__ rmax, float* __restrict__ rsum,
             float* __restrict__ cmax, float* __restrict__ csum)
{
    if (blockIdx.x < ROWSTAT_BLOCKS) {
        int r = blockIdx.x * 8 + (threadIdx.x >> 5);
        int lane = threadIdx.x & 31;
        const float* row = E + (size_t)r * TT;
        float v[32];
        float m = -1e30f;
#pragma unroll
        for (int i = 0; i < 8; ++i) {
            float4 t = *reinterpret_cast<const float4*>(row + i * 128 + lane * 4);
            v[i*4+0]=t.x; v[i*4+1]=t.y; v[i*4+2]=t.z; v[i*4+3]=t.w;
            m = fmaxf(m, fmaxf(fmaxf(t.x, t.y), fmaxf(t.z, t.w)));
        }
#pragma unroll
        for (int o = 16; o > 0; o >>= 1) m = fmaxf(m, __shfl_xor_sync(0xffffffffu, m, o));
        float s = 0.f;
#pragma unroll
        for (int i = 0; i < 32; ++i) s += __expf(v[i] - m);
#pragma unroll
        for (int o = 16; o > 0; o >>= 1) s += __shfl_xor_sync(0xffffffffu, s, o);
        if (lane == 0) { rmax[r] = m; rsum[r] = s; }
    } else {
        int id = blockIdx.x - ROWSTAT_BLOCKS;
        int b = id >> 2;
        int c = ((id & 3) << 8) + threadIdx.x;
        const float* base = E + (size_t)b * TT * TT + c;
        float m = -1e30f;
#pragma unroll 8
        for (int a = 0; a < TT; ++a) m = fmaxf(m, base[(size_t)a * TT]);
        float s = 0.f;
#pragma unroll 8
        for (int a = 0; a < TT; ++a) s += __expf(base[(size_t)a * TT] - m);
        cmax[b * TT + c] = m;
        csum[b * TT + c] = s;
    }
}

__global__ void __launch_bounds__(256)
normexp_kernel(const float* __restrict__ E, __half* __restrict__ Pall,
               const float* __restrict__ rmax, const float* __restrict__ rsum,
               const float* __restrict__ cmax, const float* __restrict__ csum)
{
    __shared__ float tile[32][33];
    int b = blockIdx.z;
    int a0 = blockIdx.y * 32, c0 = blockIdx.x * 32;
    int tx = threadIdx.x, ty = threadIdx.y;
    const float* Eb = E + (size_t)b * TT * TT;
    __half* Pb  = Pall + (size_t)b * TT * TT;                    // row softmax
    __half* P2b = Pall + (size_t)(BSZ + b) * TT * TT;            // col softmax (transposed)
#pragma unroll
    for (int k = 0; k < 4; ++k) {
        int a = a0 + k * 8 + ty;
        float v = Eb[(size_t)a * TT + c0 + tx];
        tile[k * 8 + ty][tx] = v;
        int gr = b * TT + a;
        Pb[(size_t)a * TT + c0 + tx] =
            __float2half_rn(__expf(v - rmax[gr]) * __frcp_rn(rsum[gr]));
    }
    __syncthreads();
#pragma unroll
    for (int k = 0; k < 4; ++k) {
        int c = c0 + k * 8 + ty;
        float v = tile[tx][k * 8 + ty];
        int gc = b * TT + c;
        P2b[(size_t)c * TT + a0 + tx] =
            __float2half_rn(__expf(v - cmax[gc]) * __frcp_rn(csum[gc]));
    }
}

// ======================= launch ============================================
extern "C" void kernel_launch(void* const* d_in, const int* in_sizes, int n_in,
                              void* d_out, int out_size)
{
    const float* Ain = (const float*)d_in[0];
    const float* Bin = (const float*)d_in[1];
    const float* W1  = (const float*)d_in[2];
    const float* b1  = (const float*)d_in[3];
    const float* W2  = (const float*)d_in[4];
    const float* b2  = (const float*)d_in[5];
    float* outp = (float*)d_out;

    __half *ABh, *W1Th, *W2Th, *Hh, *Fh, *Pall, *Tall;
    float *E, *rm, *rs, *cm, *cs;
    cudaGetSymbolAddress((void**)&ABh,  g_ABh);
    cudaGetSymbolAddress((void**)&W1Th, g_W1Th);
    cudaGetSymbolAddress((void**)&W2Th, g_W2Th);
    cudaGetSymbolAddress((void**)&Hh,   g_Hh);
    cudaGetSymbolAddress((void**)&Fh,   g_Fh);
    cudaGetSymbolAddress((void**)&E,    g_E);
    cudaGetSymbolAddress((void**)&Pall, g_Pall);
    cudaGetSymbolAddress((void**)&Tall, g_Tall);
    cudaGetSymbolAddress((void**)&rm,   g_rmax);
    cudaGetSymbolAddress((void**)&rs,   g_rsum);
    cudaGetSymbolAddress((void**)&cm,   g_cmax);
    cudaGetSymbolAddress((void**)&cs,   g_csum);

    cudaFuncSetAttribute(gemm_h<3, true,  true >, cudaFuncAttributeMaxDynamicSharedMemorySize, GEMM_SMEM);
    cudaFuncSetAttribute(gemm_h<3, false, false>, cudaFuncAttributeMaxDynamicSharedMemorySize, GEMM_SMEM);
    cudaFuncSetAttribute(gemm_h<1, false, false>, cudaFuncAttributeMaxDynamicSharedMemorySize, GEMM_SMEM);

    // 1) operand prep (single fused kernel)
    prep_kernel<<<PREP_BLOCKS, 256>>>(Ain, Bin, W1, W2, ABh, W1Th, W2Th, Tall);

    // 2) MLP layer 1 (A and B rows together): Hh = split(relu(X @ W1 + b1))
    gemm_h<3, true, true><<<dim3(HID/BN, 2*MROWS/BM, 1), NTHR, GEMM_SMEM>>>(
        ABh, 2*EMB, 0, W1Th, 2*EMB, 0, b1, Hh, 2*HID, 0, HID, EMB);

    // 3) MLP layer 2: Fh = split(relu(Hh @ W2 + b2))
    gemm_h<3, true, true><<<dim3(HID/BN, 2*MROWS/BM, 1), NTHR, GEMM_SMEM>>>(
        Hh, 2*HID, 0, W2Th, 2*HID, 0, b2, Fh, 2*HID, 0, HID, HID);

    // 4) e[b] = f_A[b] @ f_B[b]^T (fp32 out)
    gemm_h<3, false, false><<<dim3(TT/BN, TT/BM, BSZ), NTHR, GEMM_SMEM>>>(
        Fh, 2*HID, (unsigned long long)TT * 2 * HID,
        Fh + (size_t)MROWS * 2 * HID, 2*HID, (unsigned long long)TT * 2 * HID,
        nullptr, E, TT, (unsigned long long)TT * TT, TT, HID);

    // 5) softmax stats (row + col merged)
    stats_kernel<<<ROWSTAT_BLOCKS + COLSTAT_BLOCKS, 256>>>(E, rm, rs, cm, cs);

    // 6) normalize -> Pall = [P (16) | P2 (16)]
    normexp_kernel<<<dim3(TT/32, TT/32, BSZ), dim3(32, 8)>>>(E, Pall, rm, rs, cm, cs);

    // 7) beta (z 0..15: P @ B) and alpha (z 16..31: P2 @ A) in ONE launch;
    //    Pall / Tall / outp are each contiguous across the 32 z-slices.
    gemm_h<1, false, false><<<dim3(EMB/BN, TT/BM, 2*BSZ), NTHR, GEMM_SMEM>>>(
        Pall, TT, (unsigned long long)TT * TT, Tall, TT, (unsigned long long)EMB * TT,
        nullptr, outp, EMB, (unsigned long long)TT * EMB, EMB, TT);
}

// round 9
// speedup vs baseline: 1.1604x; 1.0124x over previous
#include <cuda_runtime.h>
#include <cuda_fp16.h>
#include <cstdint>

// Problem shapes (fixed)
#define BSZ 16
#define TT  1024
#define EMB 768
#define HID 1024
#define MROWS (BSZ*TT)   // 16384 rows per tensor

// ======================= scratch (device globals) ==========================
__device__ __align__(128) __half g_ABh [(size_t)2 * MROWS * 2 * EMB];  // split inputs (32768 x 1536)
__device__ __align__(128) __half g_W1Th[(size_t)HID * 2 * EMB];        // W1^T split (1024 x 1536)
__device__ __align__(128) __half g_W2Th[(size_t)HID * 2 * HID];        // W2^T split (1024 x 2048)
__device__ __align__(128) __half g_Hh  [(size_t)2 * MROWS * 2 * HID];  // hidden split (32768 x 2048)
__device__ __align__(128) __half g_Fh  [(size_t)2 * MROWS * 2 * HID];  // MLP out split (32768 x 2048)
__device__ __align__(128) float  g_E   [(size_t)BSZ * TT * TT];        // e (fp32)
// Pall = [P2 (16 batches, col softmax transposed) | P (16 batches, row softmax)]
__device__ __align__(128) __half g_Pall[(size_t)2 * BSZ * TT * TT];
__device__ float g_rmax[MROWS], g_rsum[MROWS];
__device__ float g_cmax[MROWS], g_csum[MROWS];

// ======================= helpers ===========================================
__device__ __forceinline__ uint32_t smem_u32(const void* p) {
    uint32_t a;
    asm("{ .reg .u64 t; cvta.to.shared.u64 t, %1; cvt.u32.u64 %0, t; }" : "=r"(a) : "l"(p));
    return a;
}
__device__ __forceinline__ void mma_f16(float* d, const uint32_t* a, const uint32_t* b) {
    asm volatile(
        "mma.sync.aligned.m16n8k16.row.col.f32.f16.f16.f32 "
        "{%0,%1,%2,%3}, {%4,%5,%6,%7}, {%8,%9}, {%0,%1,%2,%3};"
        : "+f"(d[0]), "+f"(d[1]), "+f"(d[2]), "+f"(d[3])
        : "r"(a[0]), "r"(a[1]), "r"(a[2]), "r"(a[3]), "r"(b[0]), "r"(b[1]));
}
__device__ __forceinline__ void ldsm_x4(uint32_t& r0, uint32_t& r1,
                                        uint32_t& r2, uint32_t& r3, uint32_t addr) {
    asm volatile("ldmatrix.sync.aligned.m8n8.x4.shared.b16 {%0,%1,%2,%3}, [%4];"
        : "=r"(r0), "=r"(r1), "=r"(r2), "=r"(r3) : "r"(addr));
}
__device__ __forceinline__ void ldsm_x4_trans(uint32_t& r0, uint32_t& r1,
                                              uint32_t& r2, uint32_t& r3, uint32_t addr) {
    asm volatile("ldmatrix.sync.aligned.m8n8.x4.trans.shared.b16 {%0,%1,%2,%3}, [%4];"
        : "=r"(r0), "=r"(r1), "=r"(r2), "=r"(r3) : "r"(addr));
}
__device__ __forceinline__ void split_h(float v, __half& hi, __half& lo) {
    hi = __float2half_rn(v);
    lo = __float2half_rn((v - __half2float(hi)) * 2048.0f);
}

// ======================= fp16 mma.sync GEMM ================================
// TRANSB=false: C = [act](sum_ph A_ph(M,K) * B_ph(N,K)^T + bias), B K-major.
// TRANSB=true : C = A(M,K) * B(K,N), B row-major (N contiguous), fragments
//               loaded via ldmatrix.trans. Used for beta/alpha (NPHASE=1).
// BM=128, BN=128, BK=64 halves. 8 warps = 2(m) x 4(n), warp tile 64x32.
// smem 110.6KB -> 2 CTAs/SM. 3-phase split (pre-softmax): ph0 = A_lo*B_hi,
// ph1 = A_hi*B_lo (lo pre-scaled 2048), acc *= 2^-11, ph2 = A_hi*B_hi.
#define BM 128
#define BN 128
#define BKH 64
#define NTHR 256
#define SSTR 72                            // A-stage halves/row (LDSM conflict-free)
#define SSTRB 136                          // trans B-stage halves/row (64 rows x 272B)
#define STG_BYTES ((BM + BN) * SSTR * 2)   // 36864
#define STG_A_BYTES (BM * SSTR * 2)        // 18432
#define GEMM_SMEM (3 * STG_BYTES)          // 110592

template<bool TRANSB>
__device__ __forceinline__ void cp_stage_h(uint32_t stA, uint32_t stB,
    const __half* __restrict__ ga, int lda,
    const __half* __restrict__ gb, int ldb, int tid)
{
#pragma unroll
    for (int i = 0; i < 4; ++i) {                 // A: 128 rows x 8 x 16B
        int u = tid + i * NTHR;
        int r = u >> 3, c = u & 7;
        asm volatile("cp.async.cg.shared.global [%0], [%1], 16;"
            :: "r"(stA + (uint32_t)(r * (SSTR * 2) + c * 16)),
               "l"(ga + (size_t)r * lda + c * 8) : "memory");
    }
    if (TRANSB) {
#pragma unroll
        for (int i = 0; i < 4; ++i) {             // B: 64 K-rows x 16 x 16B
            int u = tid + i * NTHR;
            int r = u >> 4, c = u & 15;
            asm volatile("cp.async.cg.shared.global [%0], [%1], 16;"
                :: "r"(stB + (uint32_t)(r * (SSTRB * 2) + c * 16)),
                   "l"(gb + (size_t)r * ldb + c * 8) : "memory");
        }
    } else {
#pragma unroll
        for (int i = 0; i < 4; ++i) {             // B: 128 N-rows x 8 x 16B
            int u = tid + i * NTHR;
            int r = u >> 3, c = u & 7;
            asm volatile("cp.async.cg.shared.global [%0], [%1], 16;"
                :: "r"(stB + (uint32_t)(r * (SSTR * 2) + c * 16)),
                   "l"(gb + (size_t)r * ldb + c * 8) : "memory");
        }
    }
}

template<int NPHASE, bool BIASRELU, bool HALFSPLITOUT, bool TRANSB, bool SWAPOUT>
__global__ void __launch_bounds__(NTHR, 2)
gemm_h(const __half* __restrict__ Aop, int lda, unsigned long long sA,
       const __half* __restrict__ Bop, int ldb, unsigned long long sB,
       const float* __restrict__ bias,
       void* __restrict__ Cv, int ldc, unsigned long long sC,
       int N, int K)
{
    extern __shared__ __align__(128) __half smh[];
    uint32_t sbase = smem_u32(smh);
    const int tid  = threadIdx.x;
    const int lane = tid & 31;
    const int wid  = tid >> 5;
    const int wm   = wid >> 2;        // 0..1 (64 rows each)
    const int wn   = wid & 3;         // 0..3 (32 cols each)
    const int gr   = lane >> 2;       // 0..7 (mma fragment row group)
    const int tc   = lane & 3;        // 0..3
    const int m0 = blockIdx.y * BM;
    const int n0 = blockIdx.x * BN;
    const int z  = blockIdx.z;

    const __half* Abase = Aop + (size_t)z * sA + (size_t)m0 * lda;
    const __half* Bbase = TRANSB
        ? (Bop + (size_t)z * sB + n0)            // row-major (K x N): col offset
        : (Bop + (size_t)z * sB + (size_t)n0 * ldb);

    const int KB = K / BKH;
    const int NT = NPHASE * KB;
    const int aoff0 = (NPHASE == 3) ? K : 0;     // phase0: A_lo
    const int boff1 = (NPHASE == 3) ? K : 0;     // phase1: B_lo

    // ---- per-lane LDSM base offsets (bytes, relative to stage A/B bases) --
    const int lg = lane >> 3;          // ldmatrix lane group 0..3
    const int r8 = lane & 7;
    uint32_t aOff[4], bOff[2];
#pragma unroll
    for (int mi = 0; mi < 4; ++mi)     // A: m8 blocks via (lg&1), k+8 via (lg>>1)
        aOff[mi] = (uint32_t)(((wm * 64 + mi * 16 + (lg & 1) * 8 + r8) * SSTR
                               + (lg >> 1) * 8) * 2);
#pragma unroll
    for (int pn = 0; pn < 2; ++pn) {
        if (TRANSB)                    // rows are K: k+8 via (lg&1); col n+8 via (lg>>1)
            bOff[pn] = (uint32_t)((((lg & 1) * 8 + r8) * SSTRB
                                   + wn * 32 + pn * 16 + (lg >> 1) * 8) * 2);
        else                           // rows are N: k+8 via (lg&1), n+8 via (lg>>1)
            bOff[pn] = (uint32_t)(((wn * 32 + pn * 16 + (lg >> 1) * 8 + r8) * SSTR
                                   + (lg & 1) * 8) * 2);
    }

    float acc[4][4][4];
#pragma unroll
    for (int i = 0; i < 4; ++i)
#pragma unroll
        for (int j = 0; j < 4; ++j)
#pragma unroll
            for (int k = 0; k < 4; ++k) acc[i][j][k] = 0.f;

    // prologue: stages 0, 1
#pragma unroll 1
    for (int s = 0; s < 2; ++s) {
        uint32_t st = sbase + (uint32_t)s * STG_BYTES;
        const __half* gb = TRANSB ? (Bbase + (size_t)s * BKH * ldb)
                                  : (Bbase + s * BKH);
        cp_stage_h<TRANSB>(st, st + STG_A_BYTES,
                           Abase + aoff0 + s * BKH, lda, gb, ldb, tid);
        asm volatile("cp.async.commit_group;" ::: "memory");
    }

#pragma unroll 1
    for (int kt = 0; kt < NT; ++kt) {
        asm volatile("cp.async.wait_group 1;" ::: "memory");
        __syncthreads();

        // prefetch kt+2
        {
            int nt = kt + 2;
            if (nt < NT) {
                int ph = nt / KB;
                int kk = nt - ph * KB;
                int oa = (ph == 0) ? aoff0 : 0;
                int ob = (ph == 1) ? boff1 : 0;
                uint32_t st = sbase + (uint32_t)(nt % 3) * STG_BYTES;
                const __half* gb = TRANSB ? (Bbase + (size_t)kk * BKH * ldb)
                                          : (Bbase + ob + kk * BKH);
                cp_stage_h<TRANSB>(st, st + STG_A_BYTES,
                                   Abase + oa + kk * BKH, lda, gb, ldb, tid);
            }
            asm volatile("cp.async.commit_group;" ::: "memory");
        }

        // scale accumulated cross terms by 2^-11 at the phase-2 boundary
        if (NPHASE == 3 && kt == 2 * KB) {
#pragma unroll
            for (int i = 0; i < 4; ++i)
#pragma unroll
                for (int j = 0; j < 4; ++j)
#pragma unroll
                    for (int k = 0; k < 4; ++k) acc[i][j][k] *= 4.8828125e-4f;
        }

        uint32_t stA = sbase + (uint32_t)(kt % 3) * STG_BYTES;
        uint32_t stB = stA + STG_A_BYTES;
#pragma unroll
        for (int ks = 0; ks < 4; ++ks) {
            const uint32_t kbA = (uint32_t)(ks * 32);            // 16 halves (cols)
            const uint32_t kbB = TRANSB ? (uint32_t)(ks * 16 * SSTRB * 2)  // 16 K-rows
                                        : (uint32_t)(ks * 32);
            uint32_t af[4][4];
            uint32_t bf[4][2];
#pragma unroll
            for (int pn = 0; pn < 2; ++pn) {
                uint32_t t0, t1, t2, t3;
                if (TRANSB) ldsm_x4_trans(t0, t1, t2, t3, stB + bOff[pn] + kbB);
                else        ldsm_x4      (t0, t1, t2, t3, stB + bOff[pn] + kbB);
                bf[2 * pn][0] = t0;  bf[2 * pn][1] = t1;
                bf[2 * pn + 1][0] = t2;  bf[2 * pn + 1][1] = t3;
            }
#pragma unroll
            for (int mi = 0; mi < 4; ++mi)
                ldsm_x4(af[mi][0], af[mi][1], af[mi][2], af[mi][3],
                        stA + aOff[mi] + kbA);
#pragma unroll
            for (int mi = 0; mi < 4; ++mi)
#pragma unroll
                for (int ni = 0; ni < 4; ++ni)
                    mma_f16(acc[mi][ni], af[mi], bf[ni]);
        }
    }

    // ---- epilogue --------------------------------------------------------
    const int ob = SWAPOUT ? ((z < BSZ) ? (BSZ + z) : (z - BSZ)) : z;
#pragma unroll
    for (int ni = 0; ni < 4; ++ni) {
        int col = n0 + wn * 32 + ni * 8 + 2 * tc;
        float b0 = 0.f, b1 = 0.f;
        if (BIASRELU) { b0 = __ldg(bias + col); b1 = __ldg(bias + col + 1); }
#pragma unroll
        for (int mi = 0; mi < 4; ++mi) {
            int row0 = m0 + wm * 64 + mi * 16 + gr;
            float v00 = acc[mi][ni][0], v01 = acc[mi][ni][1];
            float v10 = acc[mi][ni][2], v11 = acc[mi][ni][3];
            if (BIASRELU) {
                v00 = fmaxf(v00 + b0, 0.f); v01 = fmaxf(v01 + b1, 0.f);
                v10 = fmaxf(v10 + b0, 0.f); v11 = fmaxf(v11 + b1, 0.f);
            }
            if (HALFSPLITOUT) {
                __half* C = (__half*)Cv + (size_t)ob * sC;
                __half h00, l00, h01, l01, h10, l10, h11, l11;
                split_h(v00, h00, l00); split_h(v01, h01, l01);
                split_h(v10, h10, l10); split_h(v11, h11, l11);
                __half* p0 = C + (size_t)row0 * ldc + col;
                __half* p1 = C + (size_t)(row0 + 8) * ldc + col;
                *(__half2*)p0       = __halves2half2(h00, h01);
                *(__half2*)(p0 + N) = __halves2half2(l00, l01);
                *(__half2*)p1       = __halves2half2(h10, h11);
                *(__half2*)(p1 + N) = __halves2half2(l10, l11);
            } else {
                float* C = (float*)Cv + (size_t)ob * sC;
                *(float2*)(C + (size_t)row0 * ldc + col)       = make_float2(v00, v01);
                *(float2*)(C + (size_t)(row0 + 8) * ldc + col) = make_float2(v10, v11);
            }
        }
    }
}

// ======================= fused prep kernel =================================
#define NSPA ((MROWS * EMB) / 1024)            // 12288 (256 thr x float4)
#define NW1  ((EMB / 32) * (HID / 32))         // 768
#define NW2  ((HID / 32) * (HID / 32))         // 1024
#define PREP_BLOCKS (2 * NSPA + NW1 + NW2)

__global__ void __launch_bounds__(256)
prep_kernel(const float* __restrict__ A, const float* __restrict__ Bn,
            const float* __restrict__ W1, const float* __restrict__ W2,
            __half* __restrict__ ABh, __half* __restrict__ W1Th,
            __half* __restrict__ W2Th)
{
    __shared__ float tile[32][33];
    int id = blockIdx.x;
    int tid = threadIdx.x;

    if (id < 2 * NSPA) {                       // -------- input splits
        bool isA = id < NSPA;
        const float4* src = (const float4*)(isA ? A : Bn);
        size_t rowoff = isA ? 0 : (size_t)MROWS;
        size_t i = (size_t)(id - (isA ? 0 : NSPA)) * 256 + tid;
        float4 v = src[i];
        size_t row = i / (EMB / 4), c = (i % (EMB / 4)) * 4;
        __half h0, l0, h1, l1, h2, l2, h3, l3;
        split_h(v.x, h0, l0); split_h(v.y, h1, l1);
        split_h(v.z, h2, l2); split_h(v.w, h3, l3);
        __half* dst = ABh + (row + rowoff) * (2 * EMB) + c;
        *(__half2*)dst           = __halves2half2(h0, h1);
        *(__half2*)(dst + 2)     = __halves2half2(h2, h3);
        *(__half2*)(dst + EMB)   = __halves2half2(l0, l1);
        *(__half2*)(dst + EMB+2) = __halves2half2(l2, l3);
        return;
    }
    id -= 2 * NSPA;

    int tx = tid & 31, ty = tid >> 5;
    {                                          // -------- weight transpose+split
        bool isW1 = id < NW1;
        int id2 = isW1 ? id : id - NW1;
        int R = isW1 ? EMB : HID;
        const float* W = isW1 ? W1 : W2;
        __half* WT = isW1 ? W1Th : W2Th;
        int rt = R / 32;
        int r0 = (id2 % rt) * 32, c0 = (id2 / rt) * 32;
#pragma unroll
        for (int k = 0; k < 4; ++k)
            tile[k * 8 + ty][tx] = W[(size_t)(r0 + k * 8 + ty) * HID + c0 + tx];
        __syncthreads();
#pragma unroll
        for (int k = 0; k < 4; ++k) {
            int c = c0 + k * 8 + ty;
            float v = tile[tx][k * 8 + ty];
            __half h, l; split_h(v, h, l);
            WT[(size_t)c * (2 * R) + r0 + tx]     = h;
            WT[(size_t)c * (2 * R) + R + r0 + tx] = l;
        }
    }
}

// ---------------- merged softmax stats (row + col in one launch) -----------
#define ROWSTAT_BLOCKS (MROWS / 8)
#define COLSTAT_BLOCKS (BSZ * 4)

__global__ void __launch_bounds__(256)
stats_kernel(const float* __restrict__ E,
             float* __restrict__ rmax, float* __restrict__ rsum,
             float* __restrict__ cmax, float* __restrict__ csum)
{
    if (blockIdx.x < ROWSTAT_BLOCKS) {
        int r = blockIdx.x * 8 + (threadIdx.x >> 5);
        int lane = threadIdx.x & 31;
        const float* row = E + (size_t)r * TT;
        float v[32];
        float m = -1e30f;
#pragma unroll
        for (int i = 0; i < 8; ++i) {
            float4 t = *reinterpret_cast<const float4*>(row + i * 128 + lane * 4);
            v[i*4+0]=t.x; v[i*4+1]=t.y; v[i*4+2]=t.z; v[i*4+3]=t.w;
            m = fmaxf(m, fmaxf(fmaxf(t.x, t.y), fmaxf(t.z, t.w)));
        }
#pragma unroll
        for (int o = 16; o > 0; o >>= 1) m = fmaxf(m, __shfl_xor_sync(0xffffffffu, m, o));
        float s = 0.f;
#pragma unroll
        for (int i = 0; i < 32; ++i) s += __expf(v[i] - m);
#pragma unroll
        for (int o = 16; o > 0; o >>= 1) s += __shfl_xor_sync(0xffffffffu, s, o);
        if (lane == 0) { rmax[r] = m; rsum[r] = s; }
    } else {
        int id = blockIdx.x - ROWSTAT_BLOCKS;
        int b = id >> 2;
        int c = ((id & 3) << 8) + threadIdx.x;
        const float* base = E + (size_t)b * TT * TT + c;
        float m = -1e30f;
#pragma unroll 8
        for (int a = 0; a < TT; ++a) m = fmaxf(m, base[(size_t)a * TT]);
        float s = 0.f;
#pragma unroll 8
        for (int a = 0; a < TT; ++a) s += __expf(base[(size_t)a * TT] - m);
        cmax[b * TT + c] = m;
        csum[b * TT + c] = s;
    }
}

__global__ void __launch_bounds__(256)
normexp_kernel(const float* __restrict__ E, __half* __restrict__ Pall,
               const float* __restrict__ rmax, const float* __restrict__ rsum,
               const float* __restrict__ cmax, const float* __restrict__ csum)
{
    __shared__ float tile[32][33];
    int b = blockIdx.z;
    int a0 = blockIdx.y * 32, c0 = blockIdx.x * 32;
    int tx = threadIdx.x, ty = threadIdx.y;
    const float* Eb = E + (size_t)b * TT * TT;
    __half* P2b = Pall + (size_t)b * TT * TT;                  // col softmax (first 16)
    __half* Pb  = Pall + (size_t)(BSZ + b) * TT * TT;          // row softmax (second 16)
#pragma unroll
    for (int k = 0; k < 4; ++k) {
        int a = a0 + k * 8 + ty;
        float v = Eb[(size_t)a * TT + c0 + tx];
        tile[k * 8 + ty][tx] = v;
        int gr = b * TT + a;
        Pb[(size_t)a * TT + c0 + tx] =
            __float2half_rn(__expf(v - rmax[gr]) * __frcp_rn(rsum[gr]));
    }
    __syncthreads();
#pragma unroll
    for (int k = 0; k < 4; ++k) {
        int c = c0 + k * 8 + ty;
        float v = tile[tx][k * 8 + ty];
        int gc = b * TT + c;
        P2b[(size_t)c * TT + a0 + tx] =
            __float2half_rn(__expf(v - cmax[gc]) * __frcp_rn(csum[gc]));
    }
}

// ======================= launch ============================================
extern "C" void kernel_launch(void* const* d_in, const int* in_sizes, int n_in,
                              void* d_out, int out_size)
{
    const float* Ain = (const float*)d_in[0];
    const float* Bin = (const float*)d_in[1];
    const float* W1  = (const float*)d_in[2];
    const float* b1  = (const float*)d_in[3];
    const float* W2  = (const float*)d_in[4];
    const float* b2  = (const float*)d_in[5];
    float* outp = (float*)d_out;

    __half *ABh, *W1Th, *W2Th, *Hh, *Fh, *Pall;
    float *E, *rm, *rs, *cm, *cs;
    cudaGetSymbolAddress((void**)&ABh,  g_ABh);
    cudaGetSymbolAddress((void**)&W1Th, g_W1Th);
    cudaGetSymbolAddress((void**)&W2Th, g_W2Th);
    cudaGetSymbolAddress((void**)&Hh,   g_Hh);
    cudaGetSymbolAddress((void**)&Fh,   g_Fh);
    cudaGetSymbolAddress((void**)&E,    g_E);
    cudaGetSymbolAddress((void**)&Pall, g_Pall);
    cudaGetSymbolAddress((void**)&rm,   g_rmax);
    cudaGetSymbolAddress((void**)&rs,   g_rsum);
    cudaGetSymbolAddress((void**)&cm,   g_cmax);
    cudaGetSymbolAddress((void**)&cs,   g_csum);

    cudaFuncSetAttribute(gemm_h<3, true,  true,  false, false>, cudaFuncAttributeMaxDynamicSharedMemorySize, GEMM_SMEM);
    cudaFuncSetAttribute(gemm_h<3, false, false, false, false>, cudaFuncAttributeMaxDynamicSharedMemorySize, GEMM_SMEM);
    cudaFuncSetAttribute(gemm_h<1, false, false, true,  true >, cudaFuncAttributeMaxDynamicSharedMemorySize, GEMM_SMEM);

    // 1) operand prep (input splits + weight transposes only)
    prep_kernel<<<PREP_BLOCKS, 256>>>(Ain, Bin, W1, W2, ABh, W1Th, W2Th);

    // 2) MLP layer 1 (A and B rows together): Hh = split(relu(X @ W1 + b1))
    gemm_h<3, true, true, false, false><<<dim3(HID/BN, 2*MROWS/BM, 1), NTHR, GEMM_SMEM>>>(
        ABh, 2*EMB, 0, W1Th, 2*EMB, 0, b1, Hh, 2*HID, 0, HID, EMB);

    // 3) MLP layer 2: Fh = split(relu(Hh @ W2 + b2))
    gemm_h<3, true, true, false, false><<<dim3(HID/BN, 2*MROWS/BM, 1), NTHR, GEMM_SMEM>>>(
        Hh, 2*HID, 0, W2Th, 2*HID, 0, b2, Fh, 2*HID, 0, HID, HID);

    // 4) e[b] = f_A[b] @ f_B[b]^T (fp32 out)
    gemm_h<3, false, false, false, false><<<dim3(TT/BN, TT/BM, BSZ), NTHR, GEMM_SMEM>>>(
        Fh, 2*HID, (unsigned long long)TT * 2 * HID,
        Fh + (size_t)MROWS * 2 * HID, 2*HID, (unsigned long long)TT * 2 * HID,
        nullptr, E, TT, (unsigned long long)TT * TT, TT, HID);

    // 5) softmax stats (row + col merged)
    stats_kernel<<<ROWSTAT_BLOCKS + COLSTAT_BLOCKS, 256>>>(E, rm, rs, cm, cs);

    // 6) normalize -> Pall = [P2 (16) | P (16)]
    normexp_kernel<<<dim3(TT/32, TT/32, BSZ), dim3(32, 8)>>>(E, Pall, rm, rs, cm, cs);

    // 7) alpha (z 0..15: P2 @ A) and beta (z 16..31: P @ B) in ONE launch.
    //    B-operand = fp16 hi rows of ABh (A batches z 0..15, B batches 16..31),
    //    row-major (t x 2EMB), loaded NN via ldmatrix.trans.
    //    SWAPOUT remaps: z<16 -> out batch 16+z (alpha half), z>=16 -> z-16 (beta).
    gemm_h<1, false, false, true, true><<<dim3(EMB/BN, TT/BM, 2*BSZ), NTHR, GEMM_SMEM>>>(
        Pall, TT, (unsigned long long)TT * TT,
        ABh, 2*EMB, (unsigned long long)TT * 2 * EMB,
        nullptr, outp, EMB, (unsigned long long)TT * EMB, EMB, TT);
}

// round 10
// speedup vs baseline: 1.2126x; 1.0450x over previous
#include <cuda_runtime.h>
#include <cuda_fp16.h>
#include <cstdint>

// Problem shapes (fixed)
#define BSZ 16
#define TT  1024
#define EMB 768
#define HID 1024
#define MROWS (BSZ*TT)   // 16384 rows per tensor

// ======================= scratch (device globals) ==========================
__device__ __align__(128) __half g_ABh [(size_t)2 * MROWS * 2 * EMB];  // split inputs (32768 x 1536)
__device__ __align__(128) __half g_W1Th[(size_t)HID * 2 * EMB];        // W1^T split (1024 x 1536)
__device__ __align__(128) __half g_W2Th[(size_t)HID * 2 * HID];        // W2^T split (1024 x 2048)
__device__ __align__(128) __half g_Hh  [(size_t)2 * MROWS * 2 * HID];  // hidden split (32768 x 2048)
__device__ __align__(128) __half g_Fh  [(size_t)2 * MROWS * 2 * HID];  // MLP out split (32768 x 2048)
__device__ __align__(128) float  g_E   [(size_t)BSZ * TT * TT];        // e (fp32)
// Pall = [P2 (16 batches, col softmax transposed) | P (16 batches, row softmax)]
__device__ __align__(128) __half g_Pall[(size_t)2 * BSZ * TT * TT];
__device__ float g_rmax[MROWS], g_rsum[MROWS];
__device__ float g_cmax[MROWS], g_csum[MROWS];

// ======================= helpers ===========================================
__device__ __forceinline__ uint32_t smem_u32(const void* p) {
    uint32_t a;
    asm("{ .reg .u64 t; cvta.to.shared.u64 t, %1; cvt.u32.u64 %0, t; }" : "=r"(a) : "l"(p));
    return a;
}
__device__ __forceinline__ void mma_f16(float* d, const uint32_t* a, const uint32_t* b) {
    asm volatile(
        "mma.sync.aligned.m16n8k16.row.col.f32.f16.f16.f32 "
        "{%0,%1,%2,%3}, {%4,%5,%6,%7}, {%8,%9}, {%0,%1,%2,%3};"
        : "+f"(d[0]), "+f"(d[1]), "+f"(d[2]), "+f"(d[3])
        : "r"(a[0]), "r"(a[1]), "r"(a[2]), "r"(a[3]), "r"(b[0]), "r"(b[1]));
}
__device__ __forceinline__ void ldsm_x4(uint32_t& r0, uint32_t& r1,
                                        uint32_t& r2, uint32_t& r3, uint32_t addr) {
    asm volatile("ldmatrix.sync.aligned.m8n8.x4.shared.b16 {%0,%1,%2,%3}, [%4];"
        : "=r"(r0), "=r"(r1), "=r"(r2), "=r"(r3) : "r"(addr));
}
__device__ __forceinline__ void ldsm_x4_trans(uint32_t& r0, uint32_t& r1,
                                              uint32_t& r2, uint32_t& r3, uint32_t addr) {
    asm volatile("ldmatrix.sync.aligned.m8n8.x4.trans.shared.b16 {%0,%1,%2,%3}, [%4];"
        : "=r"(r0), "=r"(r1), "=r"(r2), "=r"(r3) : "r"(addr));
}
__device__ __forceinline__ void cp_async16(uint32_t dst, const void* src) {
    asm volatile("cp.async.cg.shared.global [%0], [%1], 16;"
        :: "r"(dst), "l"(src) : "memory");
}
// Split: hi = rn(v), lo = rn(v - hi)  (RAW residual, no pre-scaling)
__device__ __forceinline__ void split_h(float v, __half& hi, __half& lo) {
    hi = __float2half_rn(v);
    lo = __float2half_rn(v - __half2float(hi));
}

// ======================= fp16 mma.sync GEMM ================================
// SPLIT3=true : C = [act]( A_hi*B_hi^T + A_hi*B_lo^T + A_lo*B_hi^T + bias ),
//   A,B K-major with lo stored at column offset K. All three products
//   accumulate into ONE fp32 accumulator in a single pass over K.
// SPLIT3=false: C = A(M,K) * B(K,N), B row-major, loaded via ldmatrix.trans.
// BM=128, BN=128, BK=32 halves, 2 stages, 2 CTAs/SM, 8 warps = 2(m) x 4(n).
#define BM 128
#define BN 128
#define BKH 32
#define NTHR 256
#define SROW 80                      // bytes per 64B k-row (LDSM conflict-free)
#define SROWT 272                    // bytes per trans-B row (256B + 16 pad)
#define STG3 40960u                  // 512 rows (Ahi|Alo|Bhi|Blo) x 80B
#define STGP 18944u                  // A 128x80 + B 32x272
#define ALO_OFF 10240u               // 128*80
#define BHI_OFF 20480u               // 256*80
#define BLO_OFF 30720u               // 384*80
#define BT_OFF  10240u               // plain: B region after A
#define SMEM3 (2 * 40960)            // 81920
#define SMEMP (2 * 18944)            // 37888

template<bool SPLIT3>
__device__ __forceinline__ void cp_stage32(uint32_t st,
    const __half* __restrict__ ga, int lda,
    const __half* __restrict__ gb, int ldb, int K, int tid)
{
    if (SPLIT3) {
#pragma unroll
        for (int i = 0; i < 8; ++i) {
            int u = tid + i * NTHR;          // 0..2047
            int mat = u >> 9;                // 0:Ahi 1:Alo 2:Bhi 3:Blo
            int r = (u >> 2) & 127;
            int c = u & 3;
            const __half* src = ((mat < 2) ? ga : gb)
                              + ((mat & 1) ? K : 0)
                              + (size_t)r * ((mat < 2) ? lda : ldb) + c * 8;
            cp_async16(st + (uint32_t)((mat * 128 + r) * SROW + c * 16), src);
        }
    } else {
#pragma unroll
        for (int i = 0; i < 2; ++i) {        // A hi: 128 rows x 4 x 16B
            int u = tid + i * NTHR;
            int r = u >> 2, c = u & 3;
            cp_async16(st + (uint32_t)(r * SROW + c * 16),
                       ga + (size_t)r * lda + c * 8);
        }
#pragma unroll
        for (int i = 0; i < 2; ++i) {        // B: 32 K-rows x 16 x 16B
            int u = tid + i * NTHR;
            int r = u >> 4, c = u & 15;
            cp_async16(st + BT_OFF + (uint32_t)(r * SROWT + c * 16),
                       gb + (size_t)r * ldb + c * 8);
        }
    }
}

template<bool SPLIT3, bool BIASRELU, bool HALFSPLITOUT, bool SWAPOUT>
__global__ void __launch_bounds__(NTHR, 2)
gemm_h(const __half* __restrict__ Aop, int lda, unsigned long long sA,
       const __half* __restrict__ Bop, int ldb, unsigned long long sB,
       const float* __restrict__ bias,
       void* __restrict__ Cv, int ldc, unsigned long long sC,
       int N, int K)
{
    extern __shared__ __align__(128) __half smh[];
    uint32_t sbase = smem_u32(smh);
    constexpr uint32_t STG = SPLIT3 ? STG3 : STGP;
    const int tid  = threadIdx.x;
    const int lane = tid & 31;
    const int wid  = tid >> 5;
    const int wm   = wid >> 2;        // 0..1 (64 rows each)
    const int wn   = wid & 3;         // 0..3 (32 cols each)
    const int gr   = lane >> 2;       // 0..7
    const int tc   = lane & 3;        // 0..3
    const int m0 = blockIdx.y * BM;
    const int n0 = blockIdx.x * BN;
    const int z  = blockIdx.z;

    const __half* Abase = Aop + (size_t)z * sA + (size_t)m0 * lda;
    const __half* Bbase = SPLIT3
        ? (Bop + (size_t)z * sB + (size_t)n0 * ldb)   // K-major N-rows
        : (Bop + (size_t)z * sB + n0);                // row-major (K x N)

    const int NT = K / BKH;

    // ---- per-lane LDSM base offsets (bytes) -------------------------------
    const int lg = lane >> 3;
    const int r8 = lane & 7;
    uint32_t aOff[4], bOff[2];
#pragma unroll
    for (int mi = 0; mi < 4; ++mi)
        aOff[mi] = (uint32_t)((wm * 64 + mi * 16 + (lg & 1) * 8 + r8) * SROW
                              + (lg >> 1) * 16);
#pragma unroll
    for (int pn = 0; pn < 2; ++pn) {
        if (SPLIT3)
            bOff[pn] = (uint32_t)((wn * 32 + pn * 16 + (lg >> 1) * 8 + r8) * SROW
                                  + (lg & 1) * 16);
        else
            bOff[pn] = (uint32_t)(((lg & 1) * 8 + r8) * SROWT
                                  + (wn * 32 + pn * 16 + (lg >> 1) * 8) * 2);
    }

    float acc[4][4][4];
#pragma unroll
    for (int i = 0; i < 4; ++i)
#pragma unroll
        for (int j = 0; j < 4; ++j)
#pragma unroll
            for (int k = 0; k < 4; ++k) acc[i][j][k] = 0.f;

    // prologue: stage 0
    cp_stage32<SPLIT3>(sbase, Abase, lda, Bbase, ldb, K, tid);
    asm volatile("cp.async.commit_group;" ::: "memory");

#pragma unroll 1
    for (int kt = 0; kt < NT; ++kt) {
        asm volatile("cp.async.wait_group 0;" ::: "memory");
        __syncthreads();

        if (kt + 1 < NT) {
            uint32_t st = sbase + (uint32_t)((kt + 1) & 1) * STG;
            const __half* ga = Abase + (kt + 1) * BKH;
            const __half* gb = SPLIT3 ? (Bbase + (kt + 1) * BKH)
                                      : (Bbase + (size_t)(kt + 1) * BKH * ldb);
            cp_stage32<SPLIT3>(st, ga, lda, gb, ldb, K, tid);
            asm volatile("cp.async.commit_group;" ::: "memory");
        }

        uint32_t st = sbase + (uint32_t)(kt & 1) * STG;
#pragma unroll
        for (int ks = 0; ks < 2; ++ks) {
            if (SPLIT3) {
                const uint32_t kb = (uint32_t)(ks * 32);   // 16 halves
                uint32_t bh[4][2], bl[4][2];
#pragma unroll
                for (int pn = 0; pn < 2; ++pn) {
                    uint32_t t0, t1, t2, t3;
                    ldsm_x4(t0, t1, t2, t3, st + BHI_OFF + bOff[pn] + kb);
                    bh[2*pn][0] = t0; bh[2*pn][1] = t1;
                    bh[2*pn+1][0] = t2; bh[2*pn+1][1] = t3;
                    ldsm_x4(t0, t1, t2, t3, st + BLO_OFF + bOff[pn] + kb);
                    bl[2*pn][0] = t0; bl[2*pn][1] = t1;
                    bl[2*pn+1][0] = t2; bl[2*pn+1][1] = t3;
                }
#pragma unroll
                for (int mi = 0; mi < 4; ++mi) {
                    uint32_t ah[4], al[4];
                    ldsm_x4(ah[0], ah[1], ah[2], ah[3], st + aOff[mi] + kb);
                    ldsm_x4(al[0], al[1], al[2], al[3], st + ALO_OFF + aOff[mi] + kb);
#pragma unroll
                    for (int ni = 0; ni < 4; ++ni) mma_f16(acc[mi][ni], ah, bh[ni]);
#pragma unroll
                    for (int ni = 0; ni < 4; ++ni) mma_f16(acc[mi][ni], al, bh[ni]);
#pragma unroll
                    for (int ni = 0; ni < 4; ++ni) mma_f16(acc[mi][ni], ah, bl[ni]);
                }
            } else {
                const uint32_t kbA = (uint32_t)(ks * 32);
                const uint32_t kbB = (uint32_t)(ks * 16 * SROWT);
                uint32_t bf[4][2];
#pragma unroll
                for (int pn = 0; pn < 2; ++pn) {
                    uint32_t t0, t1, t2, t3;
                    ldsm_x4_trans(t0, t1, t2, t3, st + BT_OFF + bOff[pn] + kbB);
                    bf[2*pn][0] = t0; bf[2*pn][1] = t1;
                    bf[2*pn+1][0] = t2; bf[2*pn+1][1] = t3;
                }
#pragma unroll
                for (int mi = 0; mi < 4; ++mi) {
                    uint32_t af[4];
                    ldsm_x4(af[0], af[1], af[2], af[3], st + aOff[mi] + kbA);
#pragma unroll
                    for (int ni = 0; ni < 4; ++ni) mma_f16(acc[mi][ni], af, bf[ni]);
                }
            }
        }
    }

    // ---- epilogue --------------------------------------------------------
    const int ob = SWAPOUT ? ((z < BSZ) ? (BSZ + z) : (z - BSZ)) : z;
#pragma unroll
    for (int ni = 0; ni < 4; ++ni) {
        int col = n0 + wn * 32 + ni * 8 + 2 * tc;
        float b0 = 0.f, b1 = 0.f;
        if (BIASRELU) { b0 = __ldg(bias + col); b1 = __ldg(bias + col + 1); }
#pragma unroll
        for (int mi = 0; mi < 4; ++mi) {
            int row0 = m0 + wm * 64 + mi * 16 + gr;
            float v00 = acc[mi][ni][0], v01 = acc[mi][ni][1];
            float v10 = acc[mi][ni][2], v11 = acc[mi][ni][3];
            if (BIASRELU) {
                v00 = fmaxf(v00 + b0, 0.f); v01 = fmaxf(v01 + b1, 0.f);
                v10 = fmaxf(v10 + b0, 0.f); v11 = fmaxf(v11 + b1, 0.f);
            }
            if (HALFSPLITOUT) {
                __half* C = (__half*)Cv + (size_t)ob * sC;
                __half h00, l00, h01, l01, h10, l10, h11, l11;
                split_h(v00, h00, l00); split_h(v01, h01, l01);
                split_h(v10, h10, l10); split_h(v11, h11, l11);
                __half* p0 = C + (size_t)row0 * ldc + col;
                __half* p1 = C + (size_t)(row0 + 8) * ldc + col;
                *(__half2*)p0       = __halves2half2(h00, h01);
                *(__half2*)(p0 + N) = __halves2half2(l00, l01);
                *(__half2*)p1       = __halves2half2(h10, h11);
                *(__half2*)(p1 + N) = __halves2half2(l10, l11);
            } else {
                float* C = (float*)Cv + (size_t)ob * sC;
                *(float2*)(C + (size_t)row0 * ldc + col)       = make_float2(v00, v01);
                *(float2*)(C + (size_t)(row0 + 8) * ldc + col) = make_float2(v10, v11);
            }
        }
    }
}

// ======================= fused prep kernel =================================
#define NSPA ((MROWS * EMB) / 1024)            // 12288 (256 thr x float4)
#define NW1  ((EMB / 32) * (HID / 32))         // 768
#define NW2  ((HID / 32) * (HID / 32))         // 1024
#define PREP_BLOCKS (2 * NSPA + NW1 + NW2)

__global__ void __launch_bounds__(256)
prep_kernel(const float* __restrict__ A, const float* __restrict__ Bn,
            const float* __restrict__ W1, const float* __restrict__ W2,
            __half* __restrict__ ABh, __half* __restrict__ W1Th,
            __half* __restrict__ W2Th)
{
    __shared__ float tile[32][33];
    int id = blockIdx.x;
    int tid = threadIdx.x;

    if (id < 2 * NSPA) {                       // -------- input splits
        bool isA = id < NSPA;
        const float4* src = (const float4*)(isA ? A : Bn);
        size_t rowoff = isA ? 0 : (size_t)MROWS;
        size_t i = (size_t)(id - (isA ? 0 : NSPA)) * 256 + tid;
        float4 v = src[i];
        size_t row = i / (EMB / 4), c = (i % (EMB / 4)) * 4;
        __half h0, l0, h1, l1, h2, l2, h3, l3;
        split_h(v.x, h0, l0); split_h(v.y, h1, l1);
        split_h(v.z, h2, l2); split_h(v.w, h3, l3);
        __half* dst = ABh + (row + rowoff) * (2 * EMB) + c;
        *(__half2*)dst           = __halves2half2(h0, h1);
        *(__half2*)(dst + 2)     = __halves2half2(h2, h3);
        *(__half2*)(dst + EMB)   = __halves2half2(l0, l1);
        *(__half2*)(dst + EMB+2) = __halves2half2(l2, l3);
        return;
    }
    id -= 2 * NSPA;

    int tx = tid & 31, ty = tid >> 5;
    {                                          // -------- weight transpose+split
        bool isW1 = id < NW1;
        int id2 = isW1 ? id : id - NW1;
        int R = isW1 ? EMB : HID;
        const float* W = isW1 ? W1 : W2;
        __half* WT = isW1 ? W1Th : W2Th;
        int rt = R / 32;
        int r0 = (id2 % rt) * 32, c0 = (id2 / rt) * 32;
#pragma unroll
        for (int k = 0; k < 4; ++k)
            tile[k * 8 + ty][tx] = W[(size_t)(r0 + k * 8 + ty) * HID + c0 + tx];
        __syncthreads();
#pragma unroll
        for (int k = 0; k < 4; ++k) {
            int c = c0 + k * 8 + ty;
            float v = tile[tx][k * 8 + ty];
            __half h, l; split_h(v, h, l);
            WT[(size_t)c * (2 * R) + r0 + tx]     = h;
            WT[(size_t)c * (2 * R) + R + r0 + tx] = l;
        }
    }
}

// ---------------- merged softmax stats (row + col in one launch) -----------
#define ROWSTAT_BLOCKS (MROWS / 8)
#define COLSTAT_BLOCKS (BSZ * 4)

__global__ void __launch_bounds__(256)
stats_kernel(const float* __restrict__ E,
             float* __restrict__ rmax, float* __restrict__ rsum,
             float* __restrict__ cmax, float* __restrict__ csum)
{
    if (blockIdx.x < ROWSTAT_BLOCKS) {
        int r = blockIdx.x * 8 + (threadIdx.x >> 5);
        int lane = threadIdx.x & 31;
        const float* row = E + (size_t)r * TT;
        float v[32];
        float m = -1e30f;
#pragma unroll
        for (int i = 0; i < 8; ++i) {
            float4 t = *reinterpret_cast<const float4*>(row + i * 128 + lane * 4);
            v[i*4+0]=t.x; v[i*4+1]=t.y; v[i*4+2]=t.z; v[i*4+3]=t.w;
            m = fmaxf(m, fmaxf(fmaxf(t.x, t.y), fmaxf(t.z, t.w)));
        }
#pragma unroll
        for (int o = 16; o > 0; o >>= 1) m = fmaxf(m, __shfl_xor_sync(0xffffffffu, m, o));
        float s = 0.f;
#pragma unroll
        for (int i = 0; i < 32; ++i) s += __expf(v[i] - m);
#pragma unroll
        for (int o = 16; o > 0; o >>= 1) s += __shfl_xor_sync(0xffffffffu, s, o);
        if (lane == 0) { rmax[r] = m; rsum[r] = s; }
    } else {
        int id = blockIdx.x - ROWSTAT_BLOCKS;
        int b = id >> 2;
        int c = ((id & 3) << 8) + threadIdx.x;
        const float* base = E + (size_t)b * TT * TT + c;
        float m = -1e30f;
#pragma unroll 8
        for (int a = 0; a < TT; ++a) m = fmaxf(m, base[(size_t)a * TT]);
        float s = 0.f;
#pragma unroll 8
        for (int a = 0; a < TT; ++a) s += __expf(base[(size_t)a * TT] - m);
        cmax[b * TT + c] = m;
        csum[b * TT + c] = s;
    }
}

__global__ void __launch_bounds__(256)
normexp_kernel(const float* __restrict__ E, __half* __restrict__ Pall,
               const float* __restrict__ rmax, const float* __restrict__ rsum,
               const float* __restrict__ cmax, const float* __restrict__ csum)
{
    __shared__ float tile[32][33];
    int b = blockIdx.z;
    int a0 = blockIdx.y * 32, c0 = blockIdx.x * 32;
    int tx = threadIdx.x, ty = threadIdx.y;
    const float* Eb = E + (size_t)b * TT * TT;
    __half* P2b = Pall + (size_t)b * TT * TT;                  // col softmax (first 16)
    __half* Pb  = Pall + (size_t)(BSZ + b) * TT * TT;          // row softmax (second 16)
#pragma unroll
    for (int k = 0; k < 4; ++k) {
        int a = a0 + k * 8 + ty;
        float v = Eb[(size_t)a * TT + c0 + tx];
        tile[k * 8 + ty][tx] = v;
        int gr = b * TT + a;
        Pb[(size_t)a * TT + c0 + tx] =
            __float2half_rn(__expf(v - rmax[gr]) * __frcp_rn(rsum[gr]));
    }
    __syncthreads();
#pragma unroll
    for (int k = 0; k < 4; ++k) {
        int c = c0 + k * 8 + ty;
        float v = tile[tx][k * 8 + ty];
        int gc = b * TT + c;
        P2b[(size_t)c * TT + a0 + tx] =
            __float2half_rn(__expf(v - cmax[gc]) * __frcp_rn(csum[gc]));
    }
}

// ======================= launch ============================================
extern "C" void kernel_launch(void* const* d_in, const int* in_sizes, int n_in,
                              void* d_out, int out_size)
{
    const float* Ain = (const float*)d_in[0];
    const float* Bin = (const float*)d_in[1];
    const float* W1  = (const float*)d_in[2];
    const float* b1  = (const float*)d_in[3];
    const float* W2  = (const float*)d_in[4];
    const float* b2  = (const float*)d_in[5];
    float* outp = (float*)d_out;

    __half *ABh, *W1Th, *W2Th, *Hh, *Fh, *Pall;
    float *E, *rm, *rs, *cm, *cs;
    cudaGetSymbolAddress((void**)&ABh,  g_ABh);
    cudaGetSymbolAddress((void**)&W1Th, g_W1Th);
    cudaGetSymbolAddress((void**)&W2Th, g_W2Th);
    cudaGetSymbolAddress((void**)&Hh,   g_Hh);
    cudaGetSymbolAddress((void**)&Fh,   g_Fh);
    cudaGetSymbolAddress((void**)&E,    g_E);
    cudaGetSymbolAddress((void**)&Pall, g_Pall);
    cudaGetSymbolAddress((void**)&rm,   g_rmax);
    cudaGetSymbolAddress((void**)&rs,   g_rsum);
    cudaGetSymbolAddress((void**)&cm,   g_cmax);
    cudaGetSymbolAddress((void**)&cs,   g_csum);

    cudaFuncSetAttribute(gemm_h<true,  true,  true,  false>, cudaFuncAttributeMaxDynamicSharedMemorySize, SMEM3);
    cudaFuncSetAttribute(gemm_h<true,  false, false, false>, cudaFuncAttributeMaxDynamicSharedMemorySize, SMEM3);
    cudaFuncSetAttribute(gemm_h<false, false, false, true >, cudaFuncAttributeMaxDynamicSharedMemorySize, SMEMP);

    // 1) operand prep (input splits + weight transposes)
    prep_kernel<<<PREP_BLOCKS, 256>>>(Ain, Bin, W1, W2, ABh, W1Th, W2Th);

    // 2) MLP layer 1 (A and B rows together): Hh = split(relu(X @ W1 + b1))
    gemm_h<true, true, true, false><<<dim3(HID/BN, 2*MROWS/BM, 1), NTHR, SMEM3>>>(
        ABh, 2*EMB, 0, W1Th, 2*EMB, 0, b1, Hh, 2*HID, 0, HID, EMB);

    // 3) MLP layer 2: Fh = split(relu(Hh @ W2 + b2))
    gemm_h<true, true, true, false><<<dim3(HID/BN, 2*MROWS/BM, 1), NTHR, SMEM3>>>(
        Hh, 2*HID, 0, W2Th, 2*HID, 0, b2, Fh, 2*HID, 0, HID, HID);

    // 4) e[b] = f_A[b] @ f_B[b]^T (fp32 out)
    gemm_h<true, false, false, false><<<dim3(TT/BN, TT/BM, BSZ), NTHR, SMEM3>>>(
        Fh, 2*HID, (unsigned long long)TT * 2 * HID,
        Fh + (size_t)MROWS * 2 * HID, 2*HID, (unsigned long long)TT * 2 * HID,
        nullptr, E, TT, (unsigned long long)TT * TT, TT, HID);

    // 5) softmax stats (row + col merged)
    stats_kernel<<<ROWSTAT_BLOCKS + COLSTAT_BLOCKS, 256>>>(E, rm, rs, cm, cs);

    // 6) normalize -> Pall = [P2 (16) | P (16)]
    normexp_kernel<<<dim3(TT/32, TT/32, BSZ), dim3(32, 8)>>>(E, Pall, rm, rs, cm, cs);

    // 7) alpha (z 0..15: P2 @ A) and beta (z 16..31: P @ B) in ONE launch.
    //    B-operand = fp16 hi rows of ABh, row-major, loaded via ldmatrix.trans.
    gemm_h<false, false, false, true><<<dim3(EMB/BN, TT/BM, 2*BSZ), NTHR, SMEMP>>>(
        Pall, TT, (unsigned long long)TT * TT,
        ABh, 2*EMB, (unsigned long long)TT * 2 * EMB,
        nullptr, outp, EMB, (unsigned long long)TT * EMB, EMB, TT);
}